// round 14
// baseline (speedup 1.0000x reference)
#include <cuda_runtime.h>
#include <cstdint>

#define NN 100000
#define EE 640000
#define HH 128
#define BN_EPS 1e-5f
#define NB 391            // ceil(NN/256)
#define GB 782            // ceil(NN/128)

// ---------------- device scratch ----------------
__device__ __align__(16) uint32_t g_aggh[(size_t)NN * 64];  // agg fp16-hi packed [node][kp]
__device__ __align__(16) uint32_t g_aggl[(size_t)NN * 64];  // agg fp16-lo packed
__device__ __align__(16) float g_y[(size_t)NN * HH];
__device__ __align__(16) uint32_t g_bwh[3 * 128 * 128];  // layers 0-2 weights fp16 packed [n][kp]
__device__ __align__(16) uint32_t g_b1h[128 * 64];       // W1 fp16 packed
__device__ int   g_deg[NN];
__device__ int   g_off[NN + 1];
__device__ int   g_cur[NN];
__device__ int   g_ssrc[EE];
__device__ int   g_bpart[512];
__device__ __align__(16) float g_cs[4 * 128];
__device__ __align__(16) float g_cq[4 * 128];

// ---------------- fp16 split helpers ----------------
__device__ __forceinline__ uint32_t f16pack(float v0, float v1) {
    uint32_t r;
    asm("cvt.rn.f16x2.f32 %0, %1, %2;" : "=r"(r) : "f"(v1), "f"(v0));
    return r;
}
__device__ __forceinline__ float2 f16unpack(uint32_t p) {
    float lo, hi;
    asm("{ .reg .f16 a, b; mov.b32 {a, b}, %2; cvt.f32.f16 %0, a; cvt.f32.f16 %1, b; }"
        : "=f"(lo), "=f"(hi) : "r"(p));
    return make_float2(lo, hi);
}
__device__ __forceinline__ void f16split2(float v0, float v1, uint32_t& hp, uint32_t& lp) {
    uint32_t h = f16pack(v0, v1);
    float2 hv = f16unpack(h);
    lp = f16pack(v0 - hv.x, v1 - hv.y);
    hp = h;
}

__device__ __forceinline__ void mma16h(float* c, const uint32_t* a, uint32_t b0, uint32_t b1) {
    asm("mma.sync.aligned.m16n8k16.row.col.f32.f16.f16.f32 "
        "{%0,%1,%2,%3},{%4,%5,%6,%7},{%8,%9},{%0,%1,%2,%3};"
        : "+f"(c[0]), "+f"(c[1]), "+f"(c[2]), "+f"(c[3])
        : "r"(a[0]), "r"(a[1]), "r"(a[2]), "r"(a[3]), "r"(b0), "r"(b1));
}

__device__ __forceinline__ float4 bnrelu4(float4 v, float4 m, float4 iv) {
    v.x = fmaxf(0.f, (v.x - m.x) * iv.x);
    v.y = fmaxf(0.f, (v.y - m.y) * iv.y);
    v.z = fmaxf(0.f, (v.z - m.z) * iv.z);
    v.w = fmaxf(0.f, (v.w - m.w) * iv.w);
    return v;
}

// ---------------- prologue: weight fp16 pack + zero deg/cur/stats ----------------
__global__ void k_split(const float* __restrict__ Wl0, const float* __restrict__ Wr0,
                        const float* __restrict__ Wl1, const float* __restrict__ Wr1,
                        const float* __restrict__ Wl2, const float* __restrict__ Wr2,
                        const float* __restrict__ W1) {
    int i = blockIdx.x * 256 + threadIdx.x;
    if (i < NN) { g_deg[i] = 0; g_cur[i] = 0; }
    if (i < 512) { g_cs[i] = 0.f; g_cq[i] = 0.f; }
    if (i < 3 * 128 * 128) {
        int layer = i >> 14;
        int r = i & 16383;
        int n = r >> 7;
        int kp = r & 127;
        int gk = kp * 2;
        const float* W;
        int k = gk;
        if (gk < 128) {
            W = (layer == 0) ? Wl0 : ((layer == 1) ? Wl1 : Wl2);
        } else {
            W = (layer == 0) ? Wr0 : ((layer == 1) ? Wr1 : Wr2);
            k = gk - 128;
        }
        g_bwh[i] = f16pack(W[n * 128 + k], W[n * 128 + k + 1]);
    } else if (i < 3 * 128 * 128 + 128 * 64) {
        int j = i - 49152;
        int n = j >> 6, kp = j & 63;
        g_b1h[j] = f16pack(W1[n * 128 + kp * 2], W1[n * 128 + kp * 2 + 1]);
    }
}

// ---------------- CSR build ----------------
__global__ void k_count(const int* __restrict__ dst) {
    int e = blockIdx.x * blockDim.x + threadIdx.x;
    if (e < EE) atomicAdd(&g_deg[dst[e]], 1);
}

__global__ void k_part() {
    __shared__ int ws[8];
    int i = blockIdx.x * 256 + threadIdx.x;
    int v = (i < NN) ? g_deg[i] : 0;
    int lane = threadIdx.x & 31, wid = threadIdx.x >> 5;
    int s = v;
#pragma unroll
    for (int o = 16; o; o >>= 1) s += __shfl_xor_sync(0xFFFFFFFFu, s, o);
    if (lane == 0) ws[wid] = s;
    __syncthreads();
    if (threadIdx.x == 0) {
        int t = 0;
#pragma unroll
        for (int w = 0; w < 8; w++) t += ws[w];
        g_bpart[blockIdx.x] = t;
    }
}

__global__ void k_apply2() {
    __shared__ int wsum[8];
    __shared__ int ws2[8];
    __shared__ int sbase;
    int tid = threadIdx.x, bid = blockIdx.x;
    int lane = tid & 31, wid = tid >> 5;

    int p = 0;
    for (int j = tid; j < bid; j += 256) p += g_bpart[j];
#pragma unroll
    for (int o = 16; o; o >>= 1) p += __shfl_xor_sync(0xFFFFFFFFu, p, o);
    if (lane == 0) wsum[wid] = p;
    __syncthreads();
    if (tid == 0) {
        int t = 0;
#pragma unroll
        for (int w = 0; w < 8; w++) t += wsum[w];
        sbase = t;
    }
    __syncthreads();

    int i = bid * 256 + tid;
    int v = (i < NN) ? g_deg[i] : 0;
    int incl = v;
#pragma unroll
    for (int o = 1; o < 32; o <<= 1) {
        int u = __shfl_up_sync(0xFFFFFFFFu, incl, o);
        if (lane >= o) incl += u;
    }
    if (lane == 31) ws2[wid] = incl;
    __syncthreads();
    if (wid == 0 && lane < 8) {
        int u = ws2[lane];
#pragma unroll
        for (int o = 1; o < 8; o <<= 1) {
            int q = __shfl_up_sync(0xFFu, u, o);
            if (lane >= o) u += q;
        }
        ws2[lane] = u;
    }
    __syncthreads();
    int wpre = (wid > 0) ? ws2[wid - 1] : 0;
    if (i < NN) g_off[i + 1] = sbase + wpre + incl;
    if (bid == 0 && tid == 0) g_off[0] = 0;
}

__global__ void k_bucket(const int* __restrict__ src, const int* __restrict__ dst) {
    int e = blockIdx.x * blockDim.x + threadIdx.x;
    if (e < EE) {
        int d = dst[e];
        int p = atomicAdd(&g_cur[d], 1);
        g_ssrc[g_off[d] + p] = src[e];
    }
}

// ---------------- mean aggregation -> packed fp16 hi/lo planes ----------------
__global__ void k_agg(const float* __restrict__ X, int slotR) {
    int w = (blockIdx.x * blockDim.x + threadIdx.x) >> 5;
    int lane = threadIdx.x & 31;
    if (w >= NN) return;
    int bn = slotR >= 0;
    float4 m4 = make_float4(0.f, 0.f, 0.f, 0.f);
    float4 iv4 = make_float4(1.f, 1.f, 1.f, 1.f);
    if (bn) {
        float4 cs = *(const float4*)(g_cs + slotR * 128 + lane * 4);
        float4 cq = *(const float4*)(g_cq + slotR * 128 + lane * 4);
        m4 = make_float4(cs.x * (1.0f / NN), cs.y * (1.0f / NN),
                         cs.z * (1.0f / NN), cs.w * (1.0f / NN));
        iv4.x = rsqrtf(cq.x * (1.0f / NN) - m4.x * m4.x + BN_EPS);
        iv4.y = rsqrtf(cq.y * (1.0f / NN) - m4.y * m4.y + BN_EPS);
        iv4.z = rsqrtf(cq.z * (1.0f / NN) - m4.z * m4.z + BN_EPS);
        iv4.w = rsqrtf(cq.w * (1.0f / NN) - m4.w * m4.w + BN_EPS);
    }
    int s = g_off[w], e = g_off[w + 1];
    float4 acc = make_float4(0.f, 0.f, 0.f, 0.f);
    float4 acc2 = make_float4(0.f, 0.f, 0.f, 0.f);
    int j = s;
    for (; j + 1 < e; j += 2) {
        int s0 = g_ssrc[j];
        int s1 = g_ssrc[j + 1];
        float4 v0 = *(const float4*)(X + (size_t)s0 * HH + lane * 4);
        float4 v1 = *(const float4*)(X + (size_t)s1 * HH + lane * 4);
        if (bn) { v0 = bnrelu4(v0, m4, iv4); v1 = bnrelu4(v1, m4, iv4); }
        acc.x += v0.x; acc.y += v0.y; acc.z += v0.z; acc.w += v0.w;
        acc2.x += v1.x; acc2.y += v1.y; acc2.z += v1.z; acc2.w += v1.w;
    }
    if (j < e) {
        int s0 = g_ssrc[j];
        float4 v0 = *(const float4*)(X + (size_t)s0 * HH + lane * 4);
        if (bn) v0 = bnrelu4(v0, m4, iv4);
        acc.x += v0.x; acc.y += v0.y; acc.z += v0.z; acc.w += v0.w;
    }
    acc.x += acc2.x; acc.y += acc2.y; acc.z += acc2.z; acc.w += acc2.w;
    float invd = (e > s) ? (1.0f / (float)(e - s)) : 0.0f;
    acc.x *= invd; acc.y *= invd; acc.z *= invd; acc.w *= invd;
    uint32_t h0, l0, h1, l1;
    f16split2(acc.x, acc.y, h0, l0);
    f16split2(acc.z, acc.w, h1, l1);
    *(uint2*)(g_aggh + (size_t)w * 64 + lane * 2) = make_uint2(h0, h1);
    *(uint2*)(g_aggl + (size_t)w * 64 + lane * 2) = make_uint2(l0, l1);
}

// ---------------- fp16 2-term GEMM: D = (Ah + Al) * Bh ----------------
// A chunks 0..7: direct plane loads (A1h/A1l) if non-null; else sync from S2 (+bn).
// A chunks 8..15 (K=256): sync from S2 (+bn). B: fp16 plane Wph.
__global__ void __launch_bounds__(256, 2) k_gemm(const uint32_t* __restrict__ A1h,
                                                 const uint32_t* __restrict__ A1l,
                                                 const float* __restrict__ S2,
                                                 int bnS2,
                                                 const uint32_t* __restrict__ Wph,
                                                 const float* __restrict__ bias,
                                                 float* __restrict__ Yout,
                                                 int Ktot, int slotR, int slotW) {
    __shared__ uint32_t uAh[2][128 * 12];
    __shared__ uint32_t uAl[2][128 * 12];
    __shared__ uint32_t uBh[2][128 * 12];
    __shared__ float sMu[128], sInv[128];

    int tid = threadIdx.x;
    int lane = tid & 31, warp = tid >> 5;
    int wm = warp >> 1, wn = warp & 1;
    int m0 = blockIdx.x * 128;
    int nch = Ktot / 16;
    int wstride = Ktot / 2;

    if (bnS2 && tid < 128) {
        float mu = g_cs[slotR * 128 + tid] * (1.0f / NN);
        float var = g_cq[slotR * 128 + tid] * (1.0f / NN) - mu * mu;
        sMu[tid] = mu;
        sInv[tid] = rsqrtf(var + BN_EPS);
    }
    __syncthreads();

    const int lrow = tid >> 1;
    const int kh = tid & 1;
    const int grow = m0 + lrow;
    const bool rok = grow < NN;

    float acc[2][8][4];
#pragma unroll
    for (int mt = 0; mt < 2; mt++)
#pragma unroll
        for (int nt = 0; nt < 8; nt++)
#pragma unroll
            for (int j = 0; j < 4; j++) acc[mt][nt][j] = 0.f;

#define FILL_CHUNK(kc, buf)                                                          \
    {                                                                                \
        if ((kc) < 8 && A1h) {                                                       \
            uint4 vh = make_uint4(0u, 0u, 0u, 0u);                                   \
            uint4 vl = make_uint4(0u, 0u, 0u, 0u);                                   \
            if (rok) {                                                               \
                vh = *(const uint4*)(A1h + (size_t)grow * 64 + (kc) * 8 + kh * 4);   \
                vl = *(const uint4*)(A1l + (size_t)grow * 64 + (kc) * 8 + kh * 4);   \
            }                                                                        \
            *(uint4*)(&uAh[buf][lrow * 12 + kh * 4]) = vh;                           \
            *(uint4*)(&uAl[buf][lrow * 12 + kh * 4]) = vl;                           \
        } else {                                                                     \
            int gk = (kc) * 16 + kh * 8;                                             \
            int kk = (gk < 128) ? gk : gk - 128;                                     \
            float4 v0 = make_float4(0.f, 0.f, 0.f, 0.f);                             \
            float4 v1 = make_float4(0.f, 0.f, 0.f, 0.f);                             \
            if (rok) {                                                               \
                v0 = *(const float4*)(S2 + (size_t)grow * HH + kk);                  \
                v1 = *(const float4*)(S2 + (size_t)grow * HH + kk + 4);              \
                if (bnS2) {                                                          \
                    float4 mm0 = *(const float4*)(sMu + kk);                         \
                    float4 ii0 = *(const float4*)(sInv + kk);                        \
                    float4 mm1 = *(const float4*)(sMu + kk + 4);                     \
                    float4 ii1 = *(const float4*)(sInv + kk + 4);                    \
                    v0 = bnrelu4(v0, mm0, ii0);                                      \
                    v1 = bnrelu4(v1, mm1, ii1);                                      \
                }                                                                    \
            }                                                                        \
            uint32_t h0, h1, h2, h3, l0, l1, l2, l3;                                 \
            f16split2(v0.x, v0.y, h0, l0);                                           \
            f16split2(v0.z, v0.w, h1, l1);                                           \
            f16split2(v1.x, v1.y, h2, l2);                                           \
            f16split2(v1.z, v1.w, h3, l3);                                           \
            *(uint4*)(&uAh[buf][lrow * 12 + kh * 4]) = make_uint4(h0, h1, h2, h3);   \
            *(uint4*)(&uAl[buf][lrow * 12 + kh * 4]) = make_uint4(l0, l1, l2, l3);   \
        }                                                                            \
        uint4 bh = *(const uint4*)(Wph + (size_t)lrow * wstride + (kc) * 8 + kh * 4);\
        *(uint4*)(&uBh[buf][lrow * 12 + kh * 4]) = bh;                               \
    }

    FILL_CHUNK(0, 0);
    __syncthreads();

    for (int kc = 0; kc < nch; kc++) {
        int cur = kc & 1;

        uint32_t ah[8], al[8];
#pragma unroll
        for (int mt = 0; mt < 2; mt++)
#pragma unroll
            for (int j = 0; j < 4; j++) {
                int row = wm * 32 + mt * 16 + (lane >> 2) + (j & 1) * 8;
                int kp = (lane & 3) + (j >> 1) * 4;
                ah[mt * 4 + j] = uAh[cur][row * 12 + kp];
                al[mt * 4 + j] = uAl[cur][row * 12 + kp];
            }
#pragma unroll
        for (int nt = 0; nt < 8; nt++) {
            int n = wn * 64 + nt * 8 + (lane >> 2);
            int kp = lane & 3;
            uint32_t bh0 = uBh[cur][n * 12 + kp];
            uint32_t bh1 = uBh[cur][n * 12 + kp + 4];
#pragma unroll
            for (int mt = 0; mt < 2; mt++) {
                mma16h(acc[mt][nt], ah + mt * 4, bh0, bh1);
                mma16h(acc[mt][nt], al + mt * 4, bh0, bh1);
            }
        }

        if (kc + 1 < nch) {
            FILL_CHUNK(kc + 1, (kc + 1) & 1);
        }
        __syncthreads();
    }
#undef FILL_CHUNK

    // ---- epilogue: bias, store, column stats (single staging barrier) ----
    float bc[16];
#pragma unroll
    for (int nt = 0; nt < 8; nt++) {
        int c0 = wn * 64 + nt * 8 + 2 * (lane & 3);
        bc[nt * 2 + 0] = bias[c0];
        bc[nt * 2 + 1] = bias[c0 + 1];
    }

    float s[16], q[16];
#pragma unroll
    for (int j = 0; j < 16; j++) { s[j] = 0.f; q[j] = 0.f; }

#pragma unroll
    for (int mt = 0; mt < 2; mt++) {
        int r0 = m0 + wm * 32 + mt * 16 + (lane >> 2);
        int r1 = r0 + 8;
        bool ok0 = r0 < NN, ok1 = r1 < NN;
#pragma unroll
        for (int nt = 0; nt < 8; nt++) {
            int c0 = wn * 64 + nt * 8 + 2 * (lane & 3);
            float o0 = acc[mt][nt][0] + bc[nt * 2 + 0];
            float o1 = acc[mt][nt][1] + bc[nt * 2 + 1];
            float o2 = acc[mt][nt][2] + bc[nt * 2 + 0];
            float o3 = acc[mt][nt][3] + bc[nt * 2 + 1];
            if (ok0) {
                *(float2*)(Yout + (size_t)r0 * HH + c0) = make_float2(o0, o1);
                s[nt * 2 + 0] += o0; q[nt * 2 + 0] += o0 * o0;
                s[nt * 2 + 1] += o1; q[nt * 2 + 1] += o1 * o1;
            }
            if (ok1) {
                *(float2*)(Yout + (size_t)r1 * HH + c0) = make_float2(o2, o3);
                s[nt * 2 + 0] += o2; q[nt * 2 + 0] += o2 * o2;
                s[nt * 2 + 1] += o3; q[nt * 2 + 1] += o3 * o3;
            }
        }
    }

#pragma unroll
    for (int j = 0; j < 16; j++) {
#pragma unroll
        for (int o = 4; o <= 16; o <<= 1) {
            s[j] += __shfl_xor_sync(0xFFFFFFFFu, s[j], o);
            q[j] += __shfl_xor_sync(0xFFFFFFFFu, q[j], o);
        }
    }

    float* stg_s = (float*)uAh;          // [8][128]
    float* stg_q = (float*)uAh + 1024;   // [8][128]
    if (lane < 4) {
#pragma unroll
        for (int nt = 0; nt < 8; nt++) {
            int c = wn * 64 + nt * 8 + 2 * lane;
            stg_s[warp * 128 + c] = s[nt * 2 + 0];
            stg_s[warp * 128 + c + 1] = s[nt * 2 + 1];
            stg_q[warp * 128 + c] = q[nt * 2 + 0];
            stg_q[warp * 128 + c + 1] = q[nt * 2 + 1];
        }
    }
    __syncthreads();
    if (tid < 128) {
        int cn = tid >> 6;
        float ts = stg_s[(0 * 2 + cn) * 128 + tid] + stg_s[(1 * 2 + cn) * 128 + tid] +
                   stg_s[(2 * 2 + cn) * 128 + tid] + stg_s[(3 * 2 + cn) * 128 + tid];
        atomicAdd(&g_cs[slotW * 128 + tid], ts);
    } else {
        int t2 = tid - 128;
        int cn = t2 >> 6;
        float tq = stg_q[(0 * 2 + cn) * 128 + t2] + stg_q[(1 * 2 + cn) * 128 + t2] +
                   stg_q[(2 * 2 + cn) * 128 + t2] + stg_q[(3 * 2 + cn) * 128 + t2];
        atomicAdd(&g_cq[slotW * 128 + t2], tq);
    }
}

// ---------------- final projection (inline BN from slot 3) ----------------
__global__ void k_final(const float* __restrict__ Y, const float* __restrict__ W2,
                        const float* __restrict__ b2, float* __restrict__ out) {
    int w = (blockIdx.x * blockDim.x + threadIdx.x) >> 5;
    int lane = threadIdx.x & 31;
    if (w >= NN) return;
    float4 m4, iv4;
    {
        float4 cs = *(const float4*)(g_cs + 3 * 128 + lane * 4);
        float4 cq = *(const float4*)(g_cq + 3 * 128 + lane * 4);
        m4 = make_float4(cs.x * (1.0f / NN), cs.y * (1.0f / NN),
                         cs.z * (1.0f / NN), cs.w * (1.0f / NN));
        iv4.x = rsqrtf(cq.x * (1.0f / NN) - m4.x * m4.x + BN_EPS);
        iv4.y = rsqrtf(cq.y * (1.0f / NN) - m4.y * m4.y + BN_EPS);
        iv4.z = rsqrtf(cq.z * (1.0f / NN) - m4.z * m4.z + BN_EPS);
        iv4.w = rsqrtf(cq.w * (1.0f / NN) - m4.w * m4.w + BN_EPS);
    }
    float4 xv = *(const float4*)(Y + (size_t)w * HH + lane * 4);
    xv = bnrelu4(xv, m4, iv4);
    float4 w0 = *(const float4*)(W2 + lane * 4);
    float4 w1 = *(const float4*)(W2 + HH + lane * 4);
    float d0 = xv.x * w0.x + xv.y * w0.y + xv.z * w0.z + xv.w * w0.w;
    float d1 = xv.x * w1.x + xv.y * w1.y + xv.z * w1.z + xv.w * w1.w;
#pragma unroll
    for (int o = 16; o; o >>= 1) {
        d0 += __shfl_xor_sync(0xFFFFFFFFu, d0, o);
        d1 += __shfl_xor_sync(0xFFFFFFFFu, d1, o);
    }
    if (lane == 0) {
        out[(size_t)w * 2 + 0] = d0 + b2[0];
        out[(size_t)w * 2 + 1] = d1 + b2[1];
    }
}

// ---------------- host launch ----------------
extern "C" void kernel_launch(void* const* d_in, const int* in_sizes, int n_in,
                              void* d_out, int out_size) {
    const float* x   = (const float*)d_in[0];
    const int*   ei  = (const int*)d_in[1];
    const int*   src = ei;
    const int*   dst = ei + EE;
    const float* Wl0 = (const float*)d_in[2];
    const float* bl0 = (const float*)d_in[3];
    const float* Wr0 = (const float*)d_in[4];
    const float* Wl1 = (const float*)d_in[5];
    const float* bl1 = (const float*)d_in[6];
    const float* Wr1 = (const float*)d_in[7];
    const float* Wl2 = (const float*)d_in[8];
    const float* bl2 = (const float*)d_in[9];
    const float* Wr2 = (const float*)d_in[10];
    const float* W1  = (const float*)d_in[11];
    const float* b1  = (const float*)d_in[12];
    const float* W2  = (const float*)d_in[13];
    const float* b2  = (const float*)d_in[14];

    uint32_t *bwh = nullptr, *b1h = nullptr, *aggh = nullptr, *aggl = nullptr;
    float *y_ptr = nullptr;
    cudaGetSymbolAddress((void**)&bwh, g_bwh);
    cudaGetSymbolAddress((void**)&b1h, g_b1h);
    cudaGetSymbolAddress((void**)&aggh, g_aggh);
    cudaGetSymbolAddress((void**)&aggl, g_aggl);
    cudaGetSymbolAddress((void**)&y_ptr, g_y);

    // prologue + CSR build
    k_split<<<NB, 256>>>(Wl0, Wr0, Wl1, Wr1, Wl2, Wr2, W1);
    k_count<<<(EE + 255) / 256, 256>>>(dst);
    k_part<<<NB, 256>>>();
    k_apply2<<<NB, 256>>>();
    k_bucket<<<(EE + 255) / 256, 256>>>(src, dst);

    const int AGG_BLOCKS = (NN * 32 + 255) / 256;
    const int LSTRIDE = 128 * 128;

    // layer 0: agg raw x -> planes; GEMM [agg | x]
    k_agg<<<AGG_BLOCKS, 256>>>(x, -1);
    k_gemm<<<GB, 256>>>(aggh, aggl, x, 0, bwh, bl0, y_ptr, 256, -1, 0);

    // layer 1: agg bnrelu(y,slot0) -> planes; GEMM [agg | bnrelu(y)]
    k_agg<<<AGG_BLOCKS, 256>>>(y_ptr, 0);
    k_gemm<<<GB, 256>>>(aggh, aggl, y_ptr, 1, bwh + LSTRIDE, bl1, y_ptr, 256, 0, 1);

    // layer 2
    k_agg<<<AGG_BLOCKS, 256>>>(y_ptr, 1);
    k_gemm<<<GB, 256>>>(aggh, aggl, y_ptr, 1, bwh + 2 * LSTRIDE, bl2, y_ptr, 256, 1, 2);

    // MLP hidden (K=128, all-sync A from bnrelu(y, slot2))
    k_gemm<<<GB, 256>>>(nullptr, nullptr, y_ptr, 1, b1h, b1, y_ptr, 128, 2, 3);

    // output projection
    k_final<<<AGG_BLOCKS, 256>>>(y_ptr, W2, b2, (float*)d_out);
}

// round 15
// speedup vs baseline: 1.0610x; 1.0610x over previous
#include <cuda_runtime.h>
#include <cstdint>

#define NN 100000
#define EE 640000
#define HH 128
#define BN_EPS 1e-5f
#define NB 391            // ceil(NN/256)
#define GB 782            // ceil(NN/128)

// ---------------- device scratch ----------------
__device__ __align__(16) float g_agg[(size_t)NN * HH];
__device__ __align__(16) float g_y[(size_t)NN * HH];
__device__ __align__(16) uint32_t g_bwh[3 * 128 * 128];  // layers 0-2 weights fp16 packed [n][kp]
__device__ __align__(16) uint32_t g_b1h[128 * 64];       // W1 fp16 packed
__device__ int   g_deg[NN];
__device__ int   g_off[NN + 1];
__device__ int   g_cur[NN];
__device__ int   g_ssrc[EE];
__device__ int   g_bpart[512];
__device__ __align__(16) float g_cs[4 * 128];
__device__ __align__(16) float g_cq[4 * 128];

// ---------------- fp16 split helpers ----------------
__device__ __forceinline__ uint32_t f16pack(float v0, float v1) {
    uint32_t r;
    asm("cvt.rn.f16x2.f32 %0, %1, %2;" : "=r"(r) : "f"(v1), "f"(v0));
    return r;
}
__device__ __forceinline__ float2 f16unpack(uint32_t p) {
    float lo, hi;
    asm("{ .reg .f16 a, b; mov.b32 {a, b}, %2; cvt.f32.f16 %0, a; cvt.f32.f16 %1, b; }"
        : "=f"(lo), "=f"(hi) : "r"(p));
    return make_float2(lo, hi);
}
__device__ __forceinline__ void f16split2(float v0, float v1, uint32_t& hp, uint32_t& lp) {
    uint32_t h = f16pack(v0, v1);
    float2 hv = f16unpack(h);
    lp = f16pack(v0 - hv.x, v1 - hv.y);
    hp = h;
}

__device__ __forceinline__ void mma16h(float* c, const uint32_t* a, uint32_t b0, uint32_t b1) {
    asm("mma.sync.aligned.m16n8k16.row.col.f32.f16.f16.f32 "
        "{%0,%1,%2,%3},{%4,%5,%6,%7},{%8,%9},{%0,%1,%2,%3};"
        : "+f"(c[0]), "+f"(c[1]), "+f"(c[2]), "+f"(c[3])
        : "r"(a[0]), "r"(a[1]), "r"(a[2]), "r"(a[3]), "r"(b0), "r"(b1));
}

// bn+relu in scale/shift form: max(0, v*a + b)
__device__ __forceinline__ float4 bnr4(float4 v, float4 a, float4 b) {
    v.x = fmaxf(0.f, fmaf(v.x, a.x, b.x));
    v.y = fmaxf(0.f, fmaf(v.y, a.y, b.y));
    v.z = fmaxf(0.f, fmaf(v.z, a.z, b.z));
    v.w = fmaxf(0.f, fmaf(v.w, a.w, b.w));
    return v;
}

// ---------------- prologue: weight fp16 pack + zero deg/cur/stats ----------------
__global__ void k_split(const float* __restrict__ Wl0, const float* __restrict__ Wr0,
                        const float* __restrict__ Wl1, const float* __restrict__ Wr1,
                        const float* __restrict__ Wl2, const float* __restrict__ Wr2,
                        const float* __restrict__ W1) {
    int i = blockIdx.x * 256 + threadIdx.x;
    if (i < NN) { g_deg[i] = 0; g_cur[i] = 0; }
    if (i < 512) { g_cs[i] = 0.f; g_cq[i] = 0.f; }
    if (i < 3 * 128 * 128) {
        int layer = i >> 14;
        int r = i & 16383;
        int n = r >> 7;
        int kp = r & 127;
        int gk = kp * 2;
        const float* W;
        int k = gk;
        if (gk < 128) {
            W = (layer == 0) ? Wl0 : ((layer == 1) ? Wl1 : Wl2);
        } else {
            W = (layer == 0) ? Wr0 : ((layer == 1) ? Wr1 : Wr2);
            k = gk - 128;
        }
        g_bwh[i] = f16pack(W[n * 128 + k], W[n * 128 + k + 1]);
    } else if (i < 3 * 128 * 128 + 128 * 64) {
        int j = i - 49152;
        int n = j >> 6, kp = j & 63;
        g_b1h[j] = f16pack(W1[n * 128 + kp * 2], W1[n * 128 + kp * 2 + 1]);
    }
}

// ---------------- CSR build ----------------
__global__ void k_count(const int* __restrict__ dst) {
    int e = blockIdx.x * blockDim.x + threadIdx.x;
    if (e < EE) atomicAdd(&g_deg[dst[e]], 1);
}

__global__ void k_part() {
    __shared__ int ws[8];
    int i = blockIdx.x * 256 + threadIdx.x;
    int v = (i < NN) ? g_deg[i] : 0;
    int lane = threadIdx.x & 31, wid = threadIdx.x >> 5;
    int s = v;
#pragma unroll
    for (int o = 16; o; o >>= 1) s += __shfl_xor_sync(0xFFFFFFFFu, s, o);
    if (lane == 0) ws[wid] = s;
    __syncthreads();
    if (threadIdx.x == 0) {
        int t = 0;
#pragma unroll
        for (int w = 0; w < 8; w++) t += ws[w];
        g_bpart[blockIdx.x] = t;
    }
}

__global__ void k_apply2() {
    __shared__ int wsum[8];
    __shared__ int ws2[8];
    __shared__ int sbase;
    int tid = threadIdx.x, bid = blockIdx.x;
    int lane = tid & 31, wid = tid >> 5;

    int p = 0;
    for (int j = tid; j < bid; j += 256) p += g_bpart[j];
#pragma unroll
    for (int o = 16; o; o >>= 1) p += __shfl_xor_sync(0xFFFFFFFFu, p, o);
    if (lane == 0) wsum[wid] = p;
    __syncthreads();
    if (tid == 0) {
        int t = 0;
#pragma unroll
        for (int w = 0; w < 8; w++) t += wsum[w];
        sbase = t;
    }
    __syncthreads();

    int i = bid * 256 + tid;
    int v = (i < NN) ? g_deg[i] : 0;
    int incl = v;
#pragma unroll
    for (int o = 1; o < 32; o <<= 1) {
        int u = __shfl_up_sync(0xFFFFFFFFu, incl, o);
        if (lane >= o) incl += u;
    }
    if (lane == 31) ws2[wid] = incl;
    __syncthreads();
    if (wid == 0 && lane < 8) {
        int u = ws2[lane];
#pragma unroll
        for (int o = 1; o < 8; o <<= 1) {
            int q = __shfl_up_sync(0xFFu, u, o);
            if (lane >= o) u += q;
        }
        ws2[lane] = u;
    }
    __syncthreads();
    int wpre = (wid > 0) ? ws2[wid - 1] : 0;
    if (i < NN) g_off[i + 1] = sbase + wpre + incl;
    if (bid == 0 && tid == 0) g_off[0] = 0;
}

__global__ void k_bucket(const int* __restrict__ src, const int* __restrict__ dst) {
    int e = blockIdx.x * blockDim.x + threadIdx.x;
    if (e < EE) {
        int d = dst[e];
        int p = atomicAdd(&g_cur[d], 1);
        g_ssrc[g_off[d] + p] = src[e];
    }
}

// ---------------- mean aggregation (templated BN, scale/shift FMA) ----------------
template <int BN>
__global__ void k_agg(const float* __restrict__ X, int slotR) {
    int w = (blockIdx.x * blockDim.x + threadIdx.x) >> 5;
    int lane = threadIdx.x & 31;
    if (w >= NN) return;
    float4 a4, b4;
    if (BN) {
        float4 cs = *(const float4*)(g_cs + slotR * 128 + lane * 4);
        float4 cq = *(const float4*)(g_cq + slotR * 128 + lane * 4);
        float4 mu = make_float4(cs.x * (1.0f / NN), cs.y * (1.0f / NN),
                                cs.z * (1.0f / NN), cs.w * (1.0f / NN));
        a4.x = rsqrtf(cq.x * (1.0f / NN) - mu.x * mu.x + BN_EPS);
        a4.y = rsqrtf(cq.y * (1.0f / NN) - mu.y * mu.y + BN_EPS);
        a4.z = rsqrtf(cq.z * (1.0f / NN) - mu.z * mu.z + BN_EPS);
        a4.w = rsqrtf(cq.w * (1.0f / NN) - mu.w * mu.w + BN_EPS);
        b4 = make_float4(-mu.x * a4.x, -mu.y * a4.y, -mu.z * a4.z, -mu.w * a4.w);
    }
    int s = g_off[w], e = g_off[w + 1];
    float4 acc = make_float4(0.f, 0.f, 0.f, 0.f);
    float4 acc2 = make_float4(0.f, 0.f, 0.f, 0.f);
    int j = s;
    for (; j + 1 < e; j += 2) {
        int s0 = g_ssrc[j];
        int s1 = g_ssrc[j + 1];
        float4 v0 = *(const float4*)(X + (size_t)s0 * HH + lane * 4);
        float4 v1 = *(const float4*)(X + (size_t)s1 * HH + lane * 4);
        if (BN) { v0 = bnr4(v0, a4, b4); v1 = bnr4(v1, a4, b4); }
        acc.x += v0.x; acc.y += v0.y; acc.z += v0.z; acc.w += v0.w;
        acc2.x += v1.x; acc2.y += v1.y; acc2.z += v1.z; acc2.w += v1.w;
    }
    if (j < e) {
        int s0 = g_ssrc[j];
        float4 v0 = *(const float4*)(X + (size_t)s0 * HH + lane * 4);
        if (BN) v0 = bnr4(v0, a4, b4);
        acc.x += v0.x; acc.y += v0.y; acc.z += v0.z; acc.w += v0.w;
    }
    acc.x += acc2.x; acc.y += acc2.y; acc.z += acc2.z; acc.w += acc2.w;
    float invd = (e > s) ? (1.0f / (float)(e - s)) : 0.0f;
    acc.x *= invd; acc.y *= invd; acc.z *= invd; acc.w *= invd;
    *(float4*)(g_agg + (size_t)w * HH + lane * 4) = acc;
}

// ---------------- fp16 2-term GEMM: D = (Ah + Al) * Bh (templated BN on S2 reads) ----------------
// block 128x128, 8 warps (warp tile 32x64), K chunk 16, planes stride 12 (u32)
template <int BNS2>
__global__ void __launch_bounds__(256, 2) k_gemm(const float* __restrict__ PA,
                                                 const float* __restrict__ PB,
                                                 const uint32_t* __restrict__ Wph,
                                                 const float* __restrict__ bias,
                                                 float* __restrict__ Yout,
                                                 int Ktot, int bnA, int bnB,
                                                 int slotR, int slotW) {
    __shared__ uint32_t uAh[2][128 * 12];
    __shared__ uint32_t uAl[2][128 * 12];
    __shared__ uint32_t uBh[2][128 * 12];
    __shared__ float sA[128], sB[128];

    int tid = threadIdx.x;
    int lane = tid & 31, warp = tid >> 5;
    int wm = warp >> 1, wn = warp & 1;
    int m0 = blockIdx.x * 128;
    int nch = Ktot / 16;
    int wstride = Ktot / 2;

    if (BNS2 && tid < 128) {
        float mu = g_cs[slotR * 128 + tid] * (1.0f / NN);
        float var = g_cq[slotR * 128 + tid] * (1.0f / NN) - mu * mu;
        float iv = rsqrtf(var + BN_EPS);
        sA[tid] = iv;
        sB[tid] = -mu * iv;
    }
    __syncthreads();

    const int lrow = tid >> 1;
    const int kh = tid & 1;
    const int grow = m0 + lrow;
    const bool rok = grow < NN;

    float acc[2][8][4];
#pragma unroll
    for (int mt = 0; mt < 2; mt++)
#pragma unroll
        for (int nt = 0; nt < 8; nt++)
#pragma unroll
            for (int j = 0; j < 4; j++) acc[mt][nt][j] = 0.f;

#define FILL_CHUNK(kc, buf)                                                          \
    {                                                                                \
        int gk = (kc) * 16 + kh * 8;                                                 \
        float4 v0 = make_float4(0.f, 0.f, 0.f, 0.f);                                 \
        float4 v1 = make_float4(0.f, 0.f, 0.f, 0.f);                                 \
        if (rok) {                                                                   \
            const float* S; int kk; int bn;                                          \
            if (gk < 128) { S = PA; kk = gk; bn = bnA; }                             \
            else          { S = PB; kk = gk - 128; bn = bnB; }                       \
            v0 = *(const float4*)(S + (size_t)grow * HH + kk);                       \
            v1 = *(const float4*)(S + (size_t)grow * HH + kk + 4);                   \
            if (BNS2 && bn) {                                                        \
                float4 aa0 = *(const float4*)(sA + kk);                              \
                float4 bb0 = *(const float4*)(sB + kk);                              \
                float4 aa1 = *(const float4*)(sA + kk + 4);                          \
                float4 bb1 = *(const float4*)(sB + kk + 4);                          \
                v0 = bnr4(v0, aa0, bb0);                                             \
                v1 = bnr4(v1, aa1, bb1);                                             \
            }                                                                        \
        }                                                                            \
        uint32_t h0, h1, h2, h3, l0, l1, l2, l3;                                     \
        f16split2(v0.x, v0.y, h0, l0);                                               \
        f16split2(v0.z, v0.w, h1, l1);                                               \
        f16split2(v1.x, v1.y, h2, l2);                                               \
        f16split2(v1.z, v1.w, h3, l3);                                               \
        *(uint4*)(&uAh[buf][lrow * 12 + kh * 4]) = make_uint4(h0, h1, h2, h3);       \
        *(uint4*)(&uAl[buf][lrow * 12 + kh * 4]) = make_uint4(l0, l1, l2, l3);       \
        uint4 bh = *(const uint4*)(Wph + (size_t)lrow * wstride + (kc) * 8 + kh * 4);\
        *(uint4*)(&uBh[buf][lrow * 12 + kh * 4]) = bh;                               \
    }

    FILL_CHUNK(0, 0);
    __syncthreads();

    for (int kc = 0; kc < nch; kc++) {
        int cur = kc & 1;

        uint32_t ah[8], al[8];
#pragma unroll
        for (int mt = 0; mt < 2; mt++)
#pragma unroll
            for (int j = 0; j < 4; j++) {
                int row = wm * 32 + mt * 16 + (lane >> 2) + (j & 1) * 8;
                int kp = (lane & 3) + (j >> 1) * 4;
                ah[mt * 4 + j] = uAh[cur][row * 12 + kp];
                al[mt * 4 + j] = uAl[cur][row * 12 + kp];
            }
#pragma unroll
        for (int nt = 0; nt < 8; nt++) {
            int n = wn * 64 + nt * 8 + (lane >> 2);
            int kp = lane & 3;
            uint32_t bh0 = uBh[cur][n * 12 + kp];
            uint32_t bh1 = uBh[cur][n * 12 + kp + 4];
#pragma unroll
            for (int mt = 0; mt < 2; mt++) {
                mma16h(acc[mt][nt], ah + mt * 4, bh0, bh1);
                mma16h(acc[mt][nt], al + mt * 4, bh0, bh1);
            }
        }

        if (kc + 1 < nch) {
            FILL_CHUNK(kc + 1, (kc + 1) & 1);
        }
        __syncthreads();
    }
#undef FILL_CHUNK

    // ---- epilogue: bias, store, column stats (single staging barrier) ----
    float bc[16];
#pragma unroll
    for (int nt = 0; nt < 8; nt++) {
        int c0 = wn * 64 + nt * 8 + 2 * (lane & 3);
        bc[nt * 2 + 0] = bias[c0];
        bc[nt * 2 + 1] = bias[c0 + 1];
    }

    float s[16], q[16];
#pragma unroll
    for (int j = 0; j < 16; j++) { s[j] = 0.f; q[j] = 0.f; }

#pragma unroll
    for (int mt = 0; mt < 2; mt++) {
        int r0 = m0 + wm * 32 + mt * 16 + (lane >> 2);
        int r1 = r0 + 8;
        bool ok0 = r0 < NN, ok1 = r1 < NN;
#pragma unroll
        for (int nt = 0; nt < 8; nt++) {
            int c0 = wn * 64 + nt * 8 + 2 * (lane & 3);
            float o0 = acc[mt][nt][0] + bc[nt * 2 + 0];
            float o1 = acc[mt][nt][1] + bc[nt * 2 + 1];
            float o2 = acc[mt][nt][2] + bc[nt * 2 + 0];
            float o3 = acc[mt][nt][3] + bc[nt * 2 + 1];
            if (ok0) {
                *(float2*)(Yout + (size_t)r0 * HH + c0) = make_float2(o0, o1);
                s[nt * 2 + 0] += o0; q[nt * 2 + 0] += o0 * o0;
                s[nt * 2 + 1] += o1; q[nt * 2 + 1] += o1 * o1;
            }
            if (ok1) {
                *(float2*)(Yout + (size_t)r1 * HH + c0) = make_float2(o2, o3);
                s[nt * 2 + 0] += o2; q[nt * 2 + 0] += o2 * o2;
                s[nt * 2 + 1] += o3; q[nt * 2 + 1] += o3 * o3;
            }
        }
    }

#pragma unroll
    for (int j = 0; j < 16; j++) {
#pragma unroll
        for (int o = 4; o <= 16; o <<= 1) {
            s[j] += __shfl_xor_sync(0xFFFFFFFFu, s[j], o);
            q[j] += __shfl_xor_sync(0xFFFFFFFFu, q[j], o);
        }
    }

    float* stg_s = (float*)uAh;          // [8][128]
    float* stg_q = (float*)uAh + 1024;   // [8][128]
    if (lane < 4) {
#pragma unroll
        for (int nt = 0; nt < 8; nt++) {
            int c = wn * 64 + nt * 8 + 2 * lane;
            stg_s[warp * 128 + c] = s[nt * 2 + 0];
            stg_s[warp * 128 + c + 1] = s[nt * 2 + 1];
            stg_q[warp * 128 + c] = q[nt * 2 + 0];
            stg_q[warp * 128 + c + 1] = q[nt * 2 + 1];
        }
    }
    __syncthreads();
    if (tid < 128) {
        int cn = tid >> 6;
        float ts = stg_s[(0 * 2 + cn) * 128 + tid] + stg_s[(1 * 2 + cn) * 128 + tid] +
                   stg_s[(2 * 2 + cn) * 128 + tid] + stg_s[(3 * 2 + cn) * 128 + tid];
        atomicAdd(&g_cs[slotW * 128 + tid], ts);
    } else {
        int t2 = tid - 128;
        int cn = t2 >> 6;
        float tq = stg_q[(0 * 2 + cn) * 128 + t2] + stg_q[(1 * 2 + cn) * 128 + t2] +
                   stg_q[(2 * 2 + cn) * 128 + t2] + stg_q[(3 * 2 + cn) * 128 + t2];
        atomicAdd(&g_cq[slotW * 128 + t2], tq);
    }
}

// ---------------- final projection (inline BN from slot 3, FMA form) ----------------
__global__ void k_final(const float* __restrict__ Y, const float* __restrict__ W2,
                        const float* __restrict__ b2, float* __restrict__ out) {
    int w = (blockIdx.x * blockDim.x + threadIdx.x) >> 5;
    int lane = threadIdx.x & 31;
    if (w >= NN) return;
    float4 a4, b4;
    {
        float4 cs = *(const float4*)(g_cs + 3 * 128 + lane * 4);
        float4 cq = *(const float4*)(g_cq + 3 * 128 + lane * 4);
        float4 mu = make_float4(cs.x * (1.0f / NN), cs.y * (1.0f / NN),
                                cs.z * (1.0f / NN), cs.w * (1.0f / NN));
        a4.x = rsqrtf(cq.x * (1.0f / NN) - mu.x * mu.x + BN_EPS);
        a4.y = rsqrtf(cq.y * (1.0f / NN) - mu.y * mu.y + BN_EPS);
        a4.z = rsqrtf(cq.z * (1.0f / NN) - mu.z * mu.z + BN_EPS);
        a4.w = rsqrtf(cq.w * (1.0f / NN) - mu.w * mu.w + BN_EPS);
        b4 = make_float4(-mu.x * a4.x, -mu.y * a4.y, -mu.z * a4.z, -mu.w * a4.w);
    }
    float4 xv = *(const float4*)(Y + (size_t)w * HH + lane * 4);
    xv = bnr4(xv, a4, b4);
    float4 w0 = *(const float4*)(W2 + lane * 4);
    float4 w1 = *(const float4*)(W2 + HH + lane * 4);
    float d0 = xv.x * w0.x + xv.y * w0.y + xv.z * w0.z + xv.w * w0.w;
    float d1 = xv.x * w1.x + xv.y * w1.y + xv.z * w1.z + xv.w * w1.w;
#pragma unroll
    for (int o = 16; o; o >>= 1) {
        d0 += __shfl_xor_sync(0xFFFFFFFFu, d0, o);
        d1 += __shfl_xor_sync(0xFFFFFFFFu, d1, o);
    }
    if (lane == 0) {
        out[(size_t)w * 2 + 0] = d0 + b2[0];
        out[(size_t)w * 2 + 1] = d1 + b2[1];
    }
}

// ---------------- host launch ----------------
extern "C" void kernel_launch(void* const* d_in, const int* in_sizes, int n_in,
                              void* d_out, int out_size) {
    const float* x   = (const float*)d_in[0];
    const int*   ei  = (const int*)d_in[1];
    const int*   src = ei;
    const int*   dst = ei + EE;
    const float* Wl0 = (const float*)d_in[2];
    const float* bl0 = (const float*)d_in[3];
    const float* Wr0 = (const float*)d_in[4];
    const float* Wl1 = (const float*)d_in[5];
    const float* bl1 = (const float*)d_in[6];
    const float* Wr1 = (const float*)d_in[7];
    const float* Wl2 = (const float*)d_in[8];
    const float* bl2 = (const float*)d_in[9];
    const float* Wr2 = (const float*)d_in[10];
    const float* W1  = (const float*)d_in[11];
    const float* b1  = (const float*)d_in[12];
    const float* W2  = (const float*)d_in[13];
    const float* b2  = (const float*)d_in[14];

    uint32_t *bwh = nullptr, *b1h = nullptr;
    float *agg_ptr = nullptr, *y_ptr = nullptr;
    cudaGetSymbolAddress((void**)&bwh, g_bwh);
    cudaGetSymbolAddress((void**)&b1h, g_b1h);
    cudaGetSymbolAddress((void**)&agg_ptr, g_agg);
    cudaGetSymbolAddress((void**)&y_ptr, g_y);

    // prologue + CSR build
    k_split<<<NB, 256>>>(Wl0, Wr0, Wl1, Wr1, Wl2, Wr2, W1);
    k_count<<<(EE + 255) / 256, 256>>>(dst);
    k_part<<<NB, 256>>>();
    k_apply2<<<NB, 256>>>();
    k_bucket<<<(EE + 255) / 256, 256>>>(src, dst);

    const int AGG_BLOCKS = (NN * 32 + 255) / 256;
    const int LSTRIDE = 128 * 128;

    // layer 0
    k_agg<0><<<AGG_BLOCKS, 256>>>(x, -1);
    k_gemm<0><<<GB, 256>>>(agg_ptr, x, bwh, bl0, y_ptr, 256, 0, 0, -1, 0);

    // layer 1
    k_agg<1><<<AGG_BLOCKS, 256>>>(y_ptr, 0);
    k_gemm<1><<<GB, 256>>>(agg_ptr, y_ptr, bwh + LSTRIDE, bl1, y_ptr, 256, 0, 1, 0, 1);

    // layer 2
    k_agg<1><<<AGG_BLOCKS, 256>>>(y_ptr, 1);
    k_gemm<1><<<GB, 256>>>(agg_ptr, y_ptr, bwh + 2 * LSTRIDE, bl2, y_ptr, 256, 0, 1, 1, 2);

    // MLP hidden (K=128)
    k_gemm<1><<<GB, 256>>>(y_ptr, nullptr, b1h, b1, y_ptr, 128, 1, 0, 2, 3);

    // output projection
    k_final<<<AGG_BLOCKS, 256>>>(y_ptr, W2, b2, (float*)d_out);
}